// round 8
// baseline (speedup 1.0000x reference)
#include <cuda_runtime.h>
#include <cstdint>

// DotProductCostVolume: out[b,d,h,w] = (1/C) * sum_c left[b,c,h,w]*right[b,c,h,w-d], 0 if w<d
// B=4, C=32, H=256, W=512, D=64, fp32.
//
// CTA = (b, h, 128-wide w-tile), 128 threads, 4 CTAs/SM.
// - 3-stage cp.async channel pipeline (8 ch/chunk), ONE barrier per chunk.
// - Parity-split math: per cell (i,j) the R index m=8+i-j has parity of j, so
//   even-j cells use packed fma.rn.f32x2 with FREE aligned register-pair views
//   of the LDS.128 quads (no packing MOVs at all); odd-j cells stay scalar.
//   48 FMA-pipe instrs/channel instead of 64, zero ALU pack overhead.
// - Halo zero-filled via cp.async zfill -> w<d masking automatic.
// - Streaming stores (__stcs) protect L2 input reuse.

#define Bn 4
#define Cn 32
#define Hn 256
#define Wn 512
#define Dn 64
#define TW 128           // output w-columns per CTA
#define RW 192           // TW + 64 halo columns of right
#define NT 128           // threads per CTA
#define CH 8             // channels per pipeline chunk
#define NCH (Cn/CH)      // 4 chunks
#define NST 3            // pipeline stages

#define LCH (TW/4)       // 32 float4 chunks per L row
#define RCH (RW/4)       // 48 float4 chunks per R row
#define LST (CH*LCH)     // 256 float4 per L stage
#define RST (CH*RCH)     // 384 float4 per R stage

typedef unsigned long long ull;
union F4U { float4 f; ull u[2]; float s[4]; };

// 16B-chunk XOR swizzle (row-local chunk index q): conflict-free LDS.128.
__device__ __forceinline__ int swc(int q) { return q ^ ((q >> 3) & 7); }

__device__ __forceinline__ void cp16(uint32_t s, const void* g, bool valid) {
    asm volatile("cp.async.cg.shared.global [%0], [%1], 16, %2;"
                 :: "r"(s), "l"(g), "r"(valid ? 16 : 0));
}
__device__ __forceinline__ void cp_commit() {
    asm volatile("cp.async.commit_group;");
}
__device__ __forceinline__ void fma2(ull& d, ull a, ull b) {
    asm("fma.rn.f32x2 %0, %1, %2, %0;" : "+l"(d) : "l"(a), "l"(b));
}
__device__ __forceinline__ ull mul2(ull a, ull b) {
    ull r;
    asm("mul.rn.f32x2 %0, %1, %2;" : "=l"(r) : "l"(a), "l"(b));
    return r;
}
__device__ __forceinline__ ull pk(float lo, float hi) {
    ull r;
    asm("mov.b64 %0, {%1, %2};" : "=l"(r) : "f"(lo), "f"(hi));
    return r;
}
__device__ __forceinline__ void upk(ull v, float& lo, float& hi) {
    asm("mov.b64 {%0, %1}, %2;" : "=f"(lo), "=f"(hi) : "l"(v));
}

__global__ __launch_bounds__(NT, 4)
void cost_volume_kernel(const float* __restrict__ left,
                        const float* __restrict__ right,
                        float* __restrict__ out)
{
    __shared__ float4 Ls4[NST * LST];   // 12 KB
    __shared__ float4 Rs4[NST * RST];   // 18 KB

    const int tile = blockIdx.x;    // 0..3
    const int h    = blockIdx.y;    // 0..255
    const int b    = blockIdx.z;    // 0..3
    const int w0   = tile * TW;
    const int tid  = threadIdx.x;

    const float* lbase = left  + ((long)(b * Cn) * Hn + h) * Wn;
    const float* rbase = right + ((long)(b * Cn) * Hn + h) * Wn;

    const uint32_t lsm = (uint32_t)__cvta_generic_to_shared(Ls4);
    const uint32_t rsm = (uint32_t)__cvta_generic_to_shared(Rs4);

    // Prefetch one 8-channel chunk into stage st.
    auto prefetch = [&](int cc, int st) {
        const int c0 = cc * CH;
        #pragma unroll
        for (int it = 0; it < 2; it++) {       // L: 256 f4 / stage
            int idx = tid + it * NT;
            int ch = idx >> 5;
            int q  = idx & (LCH - 1);
            cp16(lsm + (uint32_t)(st * LST + ch * LCH + swc(q)) * 16,
                 lbase + (long)(c0 + ch) * Hn * Wn + w0 + 4 * q, true);
        }
        #pragma unroll
        for (int it = 0; it < 3; it++) {       // R: 384 f4 / stage
            int idx = tid + it * NT;
            int ch = idx / RCH;
            int q  = idx - ch * RCH;
            int gw = w0 - 64 + 4 * q;          // chunk entirely <0 or >=0
            bool v = (gw >= 0);
            cp16(rsm + (uint32_t)(st * RST + ch * RCH + swc(q)) * 16,
                 rbase + (long)(c0 + ch) * Hn * Wn + (v ? gw : 0), v);
        }
        cp_commit();
    };

    // ---- Per-thread 8w x 8d tile ----
    const int wg = tid & 15;   // w-group: w0 + 8wg .. +7
    const int dg = tid >> 4;   // d-group: 8dg .. +7

    const int lo0 = swc(2 * wg);
    const int lo1 = swc(2 * wg + 1);
    // R words rv[n] = word (8wg-8dg+56)+n, n in [0,15]; base 4-aligned.
    const int q0  = 2 * (wg - dg) + 14;          // in [0,44]
    const int ro0 = swc(q0 + 0), ro1 = swc(q0 + 1);
    const int ro2 = swc(q0 + 2), ro3 = swc(q0 + 3);

    // Even-j cells packed along w: acc2[a][e] = (acc[2a][2e], acc[2a+1][2e])
    ull acc2[4][4];
    // Odd-j cells scalar: accO[i][o] = acc[i][2o+1]
    float accO[8][4];
    #pragma unroll
    for (int a = 0; a < 4; a++)
        #pragma unroll
        for (int e = 0; e < 4; e++)
            acc2[a][e] = 0ull;
    #pragma unroll
    for (int i = 0; i < 8; i++)
        #pragma unroll
        for (int o = 0; o < 4; o++)
            accO[i][o] = 0.0f;

    prefetch(0, 0);
    prefetch(1, 1);

    for (int cc = 0; cc < NCH; cc++) {
        const int st = cc % NST;
        if (cc < NCH - 1) asm volatile("cp.async.wait_group 1;");
        else              asm volatile("cp.async.wait_group 0;");
        __syncthreads();   // single barrier per chunk (3-stage ring makes the
                           // pre-overwrite barrier provably redundant)
        if (cc + 2 < NCH) prefetch(cc + 2, (cc + 2) % NST);

        const float4* Lp = Ls4 + st * LST;
        const float4* Rp = Rs4 + st * RST;

        #pragma unroll
        for (int c = 0; c < CH; c++) {
            F4U la, lb, r0, r1, r2, r3;
            la.f = Lp[c * LCH + lo0];
            lb.f = Lp[c * LCH + lo1];
            r0.f = Rp[c * RCH + ro0];
            r1.f = Rp[c * RCH + ro1];
            r2.f = Rp[c * RCH + ro2];
            r3.f = Rp[c * RCH + ro3];

            // Free aligned pair views (register pairs of the LDS.128 quads)
            ull L2[4] = { la.u[0], la.u[1], lb.u[0], lb.u[1] };
            ull E[8]  = { r0.u[0], r0.u[1], r1.u[0], r1.u[1],
                          r2.u[0], r2.u[1], r3.u[0], r3.u[1] };
            float l[8]   = { la.s[0], la.s[1], la.s[2], la.s[3],
                             lb.s[0], lb.s[1], lb.s[2], lb.s[3] };
            float rv[16] = { r0.s[0], r0.s[1], r0.s[2], r0.s[3],
                             r1.s[0], r1.s[1], r1.s[2], r1.s[3],
                             r2.s[0], r2.s[1], r2.s[2], r2.s[3],
                             r3.s[0], r3.s[1], r3.s[2], r3.s[3] };

            #pragma unroll
            for (int a = 0; a < 4; a++) {
                // j = 2e (even): m = 8+2a-2e even -> packed, E[m/2]=E[4+a-e]
                #pragma unroll
                for (int e = 0; e < 4; e++)
                    fma2(acc2[a][e], L2[a], E[4 + a - e]);
                // j = 2o+1 (odd): m = 7+2a-2o odd -> scalar pair
                #pragma unroll
                for (int o = 0; o < 4; o++) {
                    const int m = 7 + 2 * a - 2 * o;   // in [1,13]
                    accO[2 * a][o]     += l[2 * a]     * rv[m];
                    accO[2 * a + 1][o] += l[2 * a + 1] * rv[m + 1];
                }
            }
        }
    }

    // ---- Epilogue: scale by 1/C, streaming vectorized stores ----
    const float sc = 1.0f / (float)Cn;
    const ull SC = pk(sc, sc);
    float* ob = out + ((long)(b * Dn) * Hn + h) * Wn + w0 + wg * 8;
    #pragma unroll
    for (int j = 0; j < 8; j++) {
        int d = dg * 8 + j;
        float v[8];
        if ((j & 1) == 0) {
            const int e = j >> 1;
            upk(mul2(acc2[0][e], SC), v[0], v[1]);
            upk(mul2(acc2[1][e], SC), v[2], v[3]);
            upk(mul2(acc2[2][e], SC), v[4], v[5]);
            upk(mul2(acc2[3][e], SC), v[6], v[7]);
        } else {
            const int o = j >> 1;
            #pragma unroll
            for (int i = 0; i < 8; i++) v[i] = accO[i][o] * sc;
        }
        float4* p = reinterpret_cast<float4*>(ob + (long)d * Hn * Wn);
        __stcs(p + 0, make_float4(v[0], v[1], v[2], v[3]));
        __stcs(p + 1, make_float4(v[4], v[5], v[6], v[7]));
    }
}

extern "C" void kernel_launch(void* const* d_in, const int* in_sizes, int n_in,
                              void* d_out, int out_size)
{
    const float* left  = (const float*)d_in[0];
    const float* right = (const float*)d_in[1];
    float* out = (float*)d_out;

    dim3 grid(Wn / TW, Hn, Bn);   // (4, 256, 4) = 4096 CTAs
    cost_volume_kernel<<<grid, NT>>>(left, right, out);
}